// round 1
// baseline (speedup 1.0000x reference)
#include <cuda_runtime.h>
#include <math.h>

#define Ldim 4096
#define Edim 512
#define Sdim 1024
#define Hdim 150
#define HP   160   // padded H
#define MAXN 10

// Scratch (device globals; zero-initialized at load; padded cols 150..159
// are never written -> stay zero, which the padded-K GEMM relies on).
__device__ float g_A[Ldim * HP];
__device__ float g_B[Ldim * HP];
__device__ float g_C[Ldim * HP];
__device__ float g_H1[Ldim * HP];
__device__ float g_H2[Ldim * HP];
__device__ float g_attn[Ldim];

// ---------------------------------------------------------------------------
// Generic skinny GEMM:  out[32 rows][HP] = act(in[32xK] @ W[Kx150] (+bias))
// Block: 160 threads, thread tile 8 rows x 4 cols, BK=16.
// ---------------------------------------------------------------------------
__device__ __forceinline__ void gemm_body(
    const float* __restrict__ in, int lda, int K,
    const float* __restrict__ W, const float* __restrict__ bias, int do_relu,
    float* __restrict__ out, int bm, float* sm)
{
    float* inT = sm;             // [16][32] transposed input tile
    float* Ws  = sm + 16 * 32;   // [16][160] weight tile (zero padded)

    const int tid = threadIdx.x;          // 160 threads
    const int ti  = tid / 40;             // 0..3  (row group)
    const int ci  = tid % 40;             // 0..39 (col group)
    const int r0  = ti * 8;
    const int c0  = ci * 4;
    const int row_base = bm * 32;

    float acc[8][4];
#pragma unroll
    for (int i = 0; i < 8; i++)
#pragma unroll
        for (int j = 0; j < 4; j++) acc[i][j] = 0.f;

    for (int k0 = 0; k0 < K; k0 += 16) {
        // stage input tile (transposed). 128 float4 loads.
        if (tid < 128) {
            int m = tid >> 2, q = tid & 3;
            float4 v = *(const float4*)(in + (size_t)(row_base + m) * lda + k0 + q * 4);
            inT[(q * 4 + 0) * 32 + m] = v.x;
            inT[(q * 4 + 1) * 32 + m] = v.y;
            inT[(q * 4 + 2) * 32 + m] = v.z;
            inT[(q * 4 + 3) * 32 + m] = v.w;
        }
        // stage weight tile, zero-padded to 160 cols and beyond K rows.
#pragma unroll
        for (int t = 0; t < 16; t++) {
            int idx = tid + t * 160;
            int r = idx / 160, c = idx - r * 160;
            float v = 0.f;
            if (c < Hdim && (k0 + r) < K) v = W[(size_t)(k0 + r) * Hdim + c];
            Ws[idx] = v;
        }
        __syncthreads();

#pragma unroll
        for (int k = 0; k < 16; k++) {
            float4 a0 = *(const float4*)(inT + k * 32 + r0);
            float4 a1 = *(const float4*)(inT + k * 32 + r0 + 4);
            float4 b  = *(const float4*)(Ws  + k * 160 + c0);
            float av[8] = {a0.x, a0.y, a0.z, a0.w, a1.x, a1.y, a1.z, a1.w};
            float bv[4] = {b.x, b.y, b.z, b.w};
#pragma unroll
            for (int i = 0; i < 8; i++)
#pragma unroll
                for (int j = 0; j < 4; j++) acc[i][j] += av[i] * bv[j];
        }
        __syncthreads();
    }

#pragma unroll
    for (int i = 0; i < 8; i++) {
        int m = row_base + r0 + i;
#pragma unroll
        for (int j = 0; j < 4; j++) {
            int c = c0 + j;
            if (c < Hdim) {
                float v = acc[i][j];
                if (bias) v += bias[c];
                if (do_relu) v = fmaxf(v, 0.f);
                out[(size_t)m * HP + c] = v;
            }
        }
    }
}

// One launch computes A, B, attn-H1, C (selected by blockIdx.y).
__global__ void gemm_pre_kernel(const float* __restrict__ states,
                                const float* __restrict__ embeds,
                                const float* __restrict__ aW1,
                                const float* __restrict__ ab1,
                                const float* __restrict__ sW1)
{
    extern __shared__ float sm[];
    switch (blockIdx.y) {
        case 0: gemm_body(states, Sdim, Sdim, sW1,                    nullptr, 0, g_A,  blockIdx.x, sm); break;
        case 1: gemm_body(states, Sdim, Sdim, sW1 + Sdim * Hdim,      nullptr, 0, g_B,  blockIdx.x, sm); break;
        case 2: gemm_body(states, Sdim, Sdim, aW1,                    ab1,     1, g_H1, blockIdx.x, sm); break;
        default: gemm_body(embeds, Edim, Edim, sW1 + 2 * Sdim * Hdim, nullptr, 0, g_C,  blockIdx.x, sm); break;
    }
}

// attn-scorer layer 2: H2 = relu(H1 @ aW2 + ab2). K=150 handled via zero pad.
__global__ void gemm_l2_kernel(const float* __restrict__ aW2,
                               const float* __restrict__ ab2)
{
    extern __shared__ float sm[];
    gemm_body(g_H1, HP, Hdim, aW2, ab2, 1, g_H2, blockIdx.x, sm);
}

// attn-scorer layer 3: attns[m] = H2[m] . aW3 + ab3. Warp per row.
__global__ void attn_l3_kernel(const float* __restrict__ aW3,
                               const float* __restrict__ ab3)
{
    int lane = threadIdx.x & 31;
    int m = blockIdx.x * 4 + (threadIdx.x >> 5);
    float acc = 0.f;
#pragma unroll
    for (int i = 0; i < 5; i++) {
        int c = lane + 32 * i;
        float w = (c < Hdim) ? aW3[c] : 0.f;        // H2 pad cols are zero anyway
        acc += g_H2[(size_t)m * HP + c] * w;
    }
#pragma unroll
    for (int o = 16; o > 0; o >>= 1) acc += __shfl_xor_sync(0xffffffffu, acc, o);
    if (lane == 0) g_attn[m] = acc + ab3[0];
}

// ---------------------------------------------------------------------------
// Window kernel: block = 32 consecutive starts for one n.
//   h1 = A[s] + B[s+n-1] + softmax(attn window) . C[window]  + sb1, relu
//   out = relu(h1 @ sW2 + sb2) . sW3 + sb3
// ---------------------------------------------------------------------------
#define WTHREADS 320
#define CS_STR   153   // odd-ish stride -> conflict-free across rows
#define H1_STR   161

__global__ void windows_kernel(const float* __restrict__ sb1,
                               const float* __restrict__ sW2,
                               const float* __restrict__ sb2,
                               const float* __restrict__ sW3,
                               const float* __restrict__ sb3,
                               float* __restrict__ out)
{
    extern __shared__ float sm[];
    float* W2s  = sm;                    // 150*160 = 24000
    float* Cs   = W2s + Hdim * HP;       // 41*153  = 6273
    float* h1s  = Cs  + 41 * CS_STR;     // 32*161  = 5152
    float* wsm  = h1s + 32 * H1_STR;     // 32*12   = 384
    float* attw = wsm + 32 * 12;         // 48
    float* sW3s = attw + 48;             // 160
    float* sb2s = sW3s + HP;             // 160
    float* red  = sb2s + HP;             // 10*32   = 320

    const int tid = threadIdx.x;
    const int n   = blockIdx.y + 1;          // 1..10
    const int s0  = blockIdx.x * 32;
    const int M   = Ldim - n + 1;            // #valid starts for this n
    const int nw  = 32 + n - 1;              // C / attn rows needed

    // --- stage sW2 (zero-padded cols), sW3, sb2 ---
    for (int idx = tid; idx < Hdim * HP; idx += WTHREADS) {
        int r = idx / HP, c = idx - r * HP;
        W2s[idx] = (c < Hdim) ? sW2[r * Hdim + c] : 0.f;
    }
    for (int idx = tid; idx < HP; idx += WTHREADS) {
        sW3s[idx] = (idx < Hdim) ? sW3[idx] : 0.f;
        sb2s[idx] = (idx < Hdim) ? sb2[idx] : 0.f;
    }
    // --- stage attn window ---
    for (int idx = tid; idx < nw; idx += WTHREADS) {
        int g = s0 + idx;
        attw[idx] = (g < Ldim) ? g_attn[g] : 0.f;
    }
    // --- stage h1 = A[start] + B[start+n-1] + sb1 (coalesced) ---
    for (int idx = tid; idx < 32 * HP; idx += WTHREADS) {
        int r = idx / HP, c = idx - r * HP;
        int sa = s0 + r, sb = sa + n - 1;
        float v = 0.f;
        if (c < Hdim && sb < Ldim)
            v = g_A[(size_t)sa * HP + c] + g_B[(size_t)sb * HP + c] + sb1[c];
        h1s[r * H1_STR + c] = v;
    }
    // --- stage C rows ---
    for (int idx = tid; idx < nw * Hdim; idx += WTHREADS) {
        int r = idx / Hdim, c = idx - r * Hdim;
        int g = s0 + r;
        Cs[r * CS_STR + c] = (g < Ldim) ? g_C[(size_t)g * HP + c] : 0.f;
    }
    __syncthreads();

    // --- softmax weights, one thread per window row ---
    if (tid < 32) {
        int r = tid;
        float mx = -1e30f;
        for (int j = 0; j < n; j++) mx = fmaxf(mx, attw[r + j]);
        float s = 0.f;
        for (int j = 0; j < n; j++) {
            float e = expf(attw[r + j] - mx);
            wsm[r * 12 + j] = e;
            s += e;
        }
        float inv = 1.f / s;
        for (int j = 0; j < n; j++) wsm[r * 12 + j] *= inv;
    }
    __syncthreads();

    const int r = tid & 31;   // window row within tile
    const int g = tid >> 5;   // 0..9 -> 16-col group

    // --- pooled accumulation + relu into h1s ---
    {
        float wj[MAXN];
        for (int j = 0; j < n; j++) wj[j] = wsm[r * 12 + j];
#pragma unroll
        for (int i = 0; i < 16; i++) {
            int h = g * 16 + i;
            if (h < Hdim) {
                float v = h1s[r * H1_STR + h];
                for (int j = 0; j < n; j++) v += wj[j] * Cs[(r + j) * CS_STR + h];
                h1s[r * H1_STR + h] = fmaxf(v, 0.f);
            }
        }
    }
    __syncthreads();

    // --- layer2 (150x150) + fused layer3 reduction ---
    float acc[16];
#pragma unroll
    for (int i = 0; i < 16; i++) acc[i] = 0.f;

    const float* wbase = W2s + g * 16;
#pragma unroll 2
    for (int j = 0; j < Hdim; j++) {
        float hv = h1s[r * H1_STR + j];
        const float4* wp = (const float4*)(wbase + j * HP);
        float4 b0 = wp[0], b1 = wp[1], b2 = wp[2], b3 = wp[3];
        acc[0]  += hv * b0.x; acc[1]  += hv * b0.y; acc[2]  += hv * b0.z; acc[3]  += hv * b0.w;
        acc[4]  += hv * b1.x; acc[5]  += hv * b1.y; acc[6]  += hv * b1.z; acc[7]  += hv * b1.w;
        acc[8]  += hv * b2.x; acc[9]  += hv * b2.y; acc[10] += hv * b2.z; acc[11] += hv * b2.w;
        acc[12] += hv * b3.x; acc[13] += hv * b3.y; acc[14] += hv * b3.z; acc[15] += hv * b3.w;
    }
    float pr = 0.f;
#pragma unroll
    for (int i = 0; i < 16; i++) {
        int k = g * 16 + i;
        pr += sW3s[k] * fmaxf(acc[i] + sb2s[k], 0.f);   // pad cols: sW3s=0
    }
    red[g * 32 + r] = pr;
    __syncthreads();

    if (tid < 32) {
        float s = sb3[0];
#pragma unroll
        for (int gg = 0; gg < 10; gg++) s += red[gg * 32 + tid];
        int start = s0 + tid;
        if (start < M) {
            int off = (n - 1) * (Ldim + 1) - (n * (n - 1)) / 2;
            out[off + start] = s;
        }
    }
}

// ---------------------------------------------------------------------------
extern "C" void kernel_launch(void* const* d_in, const int* in_sizes, int n_in,
                              void* d_out, int out_size)
{
    const float* embeds = (const float*)d_in[0];
    const float* states = (const float*)d_in[1];
    const float* aW1    = (const float*)d_in[2];
    const float* ab1    = (const float*)d_in[3];
    const float* aW2    = (const float*)d_in[4];
    const float* ab2    = (const float*)d_in[5];
    const float* aW3    = (const float*)d_in[6];
    const float* ab3    = (const float*)d_in[7];
    const float* sW1    = (const float*)d_in[8];
    const float* sb1    = (const float*)d_in[9];
    const float* sW2    = (const float*)d_in[10];
    const float* sb2    = (const float*)d_in[11];
    const float* sW3    = (const float*)d_in[12];
    const float* sb3    = (const float*)d_in[13];
    float* out = (float*)d_out;

    const int win_smem = 36497 * 4;   // 146 KB
    cudaFuncSetAttribute(windows_kernel,
                         cudaFuncAttributeMaxDynamicSharedMemorySize, win_smem);

    const int gemm_smem = (16 * 32 + 16 * 160) * 4;   // 12288 B

    // A, B, attn-H1, C  (blockIdx.y selects which)
    gemm_pre_kernel<<<dim3(128, 4), 160, gemm_smem>>>(states, embeds, aW1, ab1, sW1);
    // attn scorer layer 2
    gemm_l2_kernel<<<dim3(128, 1), 160, gemm_smem>>>(aW2, ab2);
    // attn scorer layer 3
    attn_l3_kernel<<<1024, 128>>>(aW3, ab3);
    // all windows, all n
    windows_kernel<<<dim3(128, 10), WTHREADS, win_smem>>>(sb1, sW2, sb2, sW3, sb3, out);
}

// round 3
// speedup vs baseline: 1.2244x; 1.2244x over previous
#include <cuda_runtime.h>
#include <math.h>

#define Ldim 4096
#define Edim 512
#define Sdim 1024
#define Hdim 150
#define HP   160       // padded H
#define MAXN 10
#define Ttot 40915     // 10L - 45
#define TP   40960     // padded to 640*64

// Scratch (device globals; zero-init at load; pad cols/rows never written -> stay 0)
__device__ float g_A[Ldim * HP];
__device__ float g_B[Ldim * HP];
__device__ float g_C[Ldim * HP];
__device__ float g_H1[Ldim * HP];
__device__ float g_H2[Ldim * HP];
__device__ float g_attn[Ldim];
__device__ float g_X[TP * HP];        // pooled+relu h1 rows for all windows
__device__ float g_W2p[HP * HP];      // padded sW2
__device__ float g_sW3p[HP];
__device__ float g_sb2p[HP];

// ---------------------------------------------------------------------------
// Skinny GEMM for precompute: out[32 rows][HP] = act(in[32xK] @ W[Kx150] (+b))
// ---------------------------------------------------------------------------
__device__ __forceinline__ void gemm_body(
    const float* __restrict__ in, int lda, int K,
    const float* __restrict__ W, const float* __restrict__ bias, int do_relu,
    float* __restrict__ out, int bm, float* sm)
{
    float* inT = sm;             // [16][32]
    float* Ws  = sm + 16 * 32;   // [16][160]

    const int tid = threadIdx.x;          // 160 threads
    const int ti  = tid / 40;
    const int ci  = tid % 40;
    const int r0  = ti * 8;
    const int c0  = ci * 4;
    const int row_base = bm * 32;

    float acc[8][4];
#pragma unroll
    for (int i = 0; i < 8; i++)
#pragma unroll
        for (int j = 0; j < 4; j++) acc[i][j] = 0.f;

    for (int k0 = 0; k0 < K; k0 += 16) {
        if (tid < 128) {
            int m = tid >> 2, q = tid & 3;
            float4 v = *(const float4*)(in + (size_t)(row_base + m) * lda + k0 + q * 4);
            inT[(q * 4 + 0) * 32 + m] = v.x;
            inT[(q * 4 + 1) * 32 + m] = v.y;
            inT[(q * 4 + 2) * 32 + m] = v.z;
            inT[(q * 4 + 3) * 32 + m] = v.w;
        }
#pragma unroll
        for (int t = 0; t < 16; t++) {
            int idx = tid + t * 160;
            int r = idx / 160, c = idx - r * 160;
            float v = 0.f;
            if (c < Hdim && (k0 + r) < K) v = W[(size_t)(k0 + r) * Hdim + c];
            Ws[idx] = v;
        }
        __syncthreads();

#pragma unroll
        for (int k = 0; k < 16; k++) {
            float4 a0 = *(const float4*)(inT + k * 32 + r0);
            float4 a1 = *(const float4*)(inT + k * 32 + r0 + 4);
            float4 b  = *(const float4*)(Ws  + k * 160 + c0);
            float av[8] = {a0.x, a0.y, a0.z, a0.w, a1.x, a1.y, a1.z, a1.w};
            float bv[4] = {b.x, b.y, b.z, b.w};
#pragma unroll
            for (int i = 0; i < 8; i++)
#pragma unroll
                for (int j = 0; j < 4; j++) acc[i][j] += av[i] * bv[j];
        }
        __syncthreads();
    }

#pragma unroll
    for (int i = 0; i < 8; i++) {
        int m = row_base + r0 + i;
#pragma unroll
        for (int j = 0; j < 4; j++) {
            int c = c0 + j;
            if (c < Hdim) {
                float v = acc[i][j];
                if (bias) v += bias[c];
                if (do_relu) v = fmaxf(v, 0.f);
                out[(size_t)m * HP + c] = v;
            }
        }
    }
}

__global__ void gemm_pre_kernel(const float* __restrict__ states,
                                const float* __restrict__ embeds,
                                const float* __restrict__ aW1,
                                const float* __restrict__ ab1,
                                const float* __restrict__ sW1)
{
    extern __shared__ float sm[];
    switch (blockIdx.y) {
        case 0: gemm_body(states, Sdim, Sdim, sW1,                    nullptr, 0, g_A,  blockIdx.x, sm); break;
        case 1: gemm_body(states, Sdim, Sdim, sW1 + Sdim * Hdim,      nullptr, 0, g_B,  blockIdx.x, sm); break;
        case 2: gemm_body(states, Sdim, Sdim, aW1,                    ab1,     1, g_H1, blockIdx.x, sm); break;
        default: gemm_body(embeds, Edim, Edim, sW1 + 2 * Sdim * Hdim, nullptr, 0, g_C,  blockIdx.x, sm); break;
    }
}

__global__ void gemm_l2_kernel(const float* __restrict__ aW2,
                               const float* __restrict__ ab2)
{
    extern __shared__ float sm[];
    gemm_body(g_H1, HP, Hdim, aW2, ab2, 1, g_H2, blockIdx.x, sm);
}

__global__ void attn_l3_kernel(const float* __restrict__ aW3,
                               const float* __restrict__ ab3)
{
    int lane = threadIdx.x & 31;
    int m = blockIdx.x * 4 + (threadIdx.x >> 5);
    float acc = 0.f;
#pragma unroll
    for (int i = 0; i < 5; i++) {
        int c = lane + 32 * i;
        float w = (c < Hdim) ? aW3[c] : 0.f;
        acc += g_H2[(size_t)m * HP + c] * w;
    }
#pragma unroll
    for (int o = 16; o > 0; o >>= 1) acc += __shfl_xor_sync(0xffffffffu, acc, o);
    if (lane == 0) g_attn[m] = acc + ab3[0];
}

// Pad sW2 -> [160][160], sW3/sb2 -> [160]
__global__ void pad_kernel(const float* __restrict__ sW2,
                           const float* __restrict__ sW3,
                           const float* __restrict__ sb2)
{
    int idx = blockIdx.x * 256 + threadIdx.x;
    if (idx < HP * HP) {
        int r = idx / HP, c = idx - r * HP;
        g_W2p[idx] = (r < Hdim && c < Hdim) ? sW2[r * Hdim + c] : 0.f;
    }
    if (idx < HP) {
        g_sW3p[idx] = (idx < Hdim) ? sW3[idx] : 0.f;
        g_sb2p[idx] = (idx < Hdim) ? sb2[idx] : 0.f;
    }
}

// ---------------------------------------------------------------------------
// Pool kernel: X[t] = relu(A[s] + B[s+n-1] + softmax(attn win).C + sb1)
// block = 128 starts for one n, 256 threads (8 warps; warp-per-row passes)
// ---------------------------------------------------------------------------
__global__ void pool_kernel(const float* __restrict__ sb1)
{
    __shared__ float attw[140];
    __shared__ float wsm[128 * 12];

    const int tid = threadIdx.x;
    const int n   = blockIdx.y + 1;
    const int s0  = blockIdx.x * 128;
    const int M   = Ldim - n + 1;
    const int nw  = 128 + n - 1;
    const int off = (n - 1) * (Ldim + 1) - (n * (n - 1)) / 2;

    for (int idx = tid; idx < nw; idx += 256) {
        int g = s0 + idx;
        attw[idx] = (g < Ldim) ? g_attn[g] : 0.f;
    }
    __syncthreads();

    if (tid < 128) {
        int r = tid;
        float mx = -1e30f;
        for (int j = 0; j < n; j++) mx = fmaxf(mx, attw[r + j]);
        float s = 0.f;
        for (int j = 0; j < n; j++) {
            float e = expf(attw[r + j] - mx);
            wsm[r * 12 + j] = e;
            s += e;
        }
        float inv = 1.f / s;
        for (int j = 0; j < n; j++) wsm[r * 12 + j] *= inv;
    }
    __syncthreads();

    const int warp = tid >> 5, lane = tid & 31;
    for (int r = warp; r < 128; r += 8) {
        int start = s0 + r;
        if (start >= M) continue;
        float wj[MAXN];
        for (int j = 0; j < n; j++) wj[j] = wsm[r * 12 + j];
        size_t tb = (size_t)(off + start) * HP;
        size_t ab = (size_t)start * HP;
        size_t bb = (size_t)(start + n - 1) * HP;
#pragma unroll
        for (int k = 0; k < 5; k++) {
            int c = lane + 32 * k;
            float v = 0.f;
            if (c < Hdim) {
                v = g_A[ab + c] + g_B[bb + c] + sb1[c];
                for (int j = 0; j < n; j++)
                    v += wj[j] * g_C[(size_t)(start + j) * HP + c];
                v = fmaxf(v, 0.f);
            }
            g_X[tb + c] = v;
        }
    }
}

// ---------------------------------------------------------------------------
// Big GEMM + fused layer3: out[t] = sW3 . relu(X[t] @ W2 + sb2) + sb3
// BM=64, BN=160, BK=16, 320 threads, 8x4 thread tile.
// inT stride 68: multiple of 4 (float4-aligned) and 68 % 32 = 4 banks offset.
// ---------------------------------------------------------------------------
#define G2T 320
#define ITS 68

__global__ void gemm2_kernel(const float* __restrict__ sb3,
                             float* __restrict__ out)
{
    __shared__ float inT[16 * ITS];
    __shared__ float Ws[16 * 160];
    __shared__ float red[64 * 41];
    __shared__ float sW3s[HP];
    __shared__ float sb2s[HP];

    const int tid = threadIdx.x;
    const int ti  = tid / 40;            // 0..7 (8 rows each)
    const int ci  = tid % 40;            // 0..39 (4 cols each)
    const int r0  = ti * 8;
    const int c0  = ci * 4;
    const size_t t0 = (size_t)blockIdx.x * 64;

    if (tid < HP) { sW3s[tid] = g_sW3p[tid]; sb2s[tid] = g_sb2p[tid]; }

    float acc[8][4];
#pragma unroll
    for (int i = 0; i < 8; i++)
#pragma unroll
        for (int j = 0; j < 4; j++) acc[i][j] = 0.f;

    for (int k0 = 0; k0 < HP; k0 += 16) {
        if (tid < 256) {
            int m = tid >> 2, q = tid & 3;
            float4 v = *(const float4*)(g_X + (t0 + m) * HP + k0 + q * 4);
            inT[(q * 4 + 0) * ITS + m] = v.x;
            inT[(q * 4 + 1) * ITS + m] = v.y;
            inT[(q * 4 + 2) * ITS + m] = v.z;
            inT[(q * 4 + 3) * ITS + m] = v.w;
        }
#pragma unroll
        for (int it = 0; it < 2; it++) {
            int idx = tid + it * G2T;    // 0..639 float4 slots
            int k = idx / 40, q = idx - k * 40;
            *(float4*)(Ws + k * 160 + q * 4) =
                *(const float4*)(g_W2p + (k0 + k) * HP + q * 4);
        }
        __syncthreads();

#pragma unroll
        for (int k = 0; k < 16; k++) {
            float4 a0 = *(const float4*)(inT + k * ITS + r0);
            float4 a1 = *(const float4*)(inT + k * ITS + r0 + 4);
            float4 b  = *(const float4*)(Ws  + k * 160 + c0);
            float av[8] = {a0.x, a0.y, a0.z, a0.w, a1.x, a1.y, a1.z, a1.w};
            float bv[4] = {b.x, b.y, b.z, b.w};
#pragma unroll
            for (int i = 0; i < 8; i++)
#pragma unroll
                for (int j = 0; j < 4; j++) acc[i][j] += av[i] * bv[j];
        }
        __syncthreads();
    }

    // epilogue: bias + relu + dot with sW3, partial per col-group
#pragma unroll
    for (int i = 0; i < 8; i++) {
        float p = 0.f;
#pragma unroll
        for (int j = 0; j < 4; j++) {
            int c = c0 + j;
            p += sW3s[c] * fmaxf(acc[i][j] + sb2s[c], 0.f);
        }
        red[(r0 + i) * 41 + ci] = p;
    }
    __syncthreads();

    if (tid < 64) {
        float s = sb3[0];
#pragma unroll
        for (int cc = 0; cc < 40; cc++) s += red[tid * 41 + cc];
        size_t t = t0 + tid;
        if (t < Ttot) out[t] = s;
    }
}

// ---------------------------------------------------------------------------
extern "C" void kernel_launch(void* const* d_in, const int* in_sizes, int n_in,
                              void* d_out, int out_size)
{
    const float* embeds = (const float*)d_in[0];
    const float* states = (const float*)d_in[1];
    const float* aW1    = (const float*)d_in[2];
    const float* ab1    = (const float*)d_in[3];
    const float* aW2    = (const float*)d_in[4];
    const float* ab2    = (const float*)d_in[5];
    const float* aW3    = (const float*)d_in[6];
    const float* ab3    = (const float*)d_in[7];
    const float* sW1    = (const float*)d_in[8];
    const float* sb1    = (const float*)d_in[9];
    const float* sW2    = (const float*)d_in[10];
    const float* sb2    = (const float*)d_in[11];
    const float* sW3    = (const float*)d_in[12];
    const float* sb3    = (const float*)d_in[13];
    float* out = (float*)d_out;

    const int gemm_smem = (16 * 32 + 16 * 160) * 4;

    // padded weight copies (independent of everything else)
    pad_kernel<<<(HP * HP + 255) / 256, 256>>>(sW2, sW3, sb2);
    // A, B, attn-H1, C
    gemm_pre_kernel<<<dim3(128, 4), 160, gemm_smem>>>(states, embeds, aW1, ab1, sW1);
    // attn scorer layers 2, 3
    gemm_l2_kernel<<<dim3(128, 1), 160, gemm_smem>>>(aW2, ab2);
    attn_l3_kernel<<<1024, 128>>>(aW3, ab3);
    // pooled h1 rows for all (n, start)
    pool_kernel<<<dim3(32, 10), 256>>>(sb1);
    // layer2 + layer3 over all 40915 rows
    gemm2_kernel<<<TP / 64, G2T>>>(sb3, out);
}